// round 6
// baseline (speedup 1.0000x reference)
#include <cuda_runtime.h>
#include <cuda_bf16.h>
#include <cstdint>

// GraphSAGE 2-layer.
//   L1: agg1 = segmean(x) [64]; h = relu([agg1|x] @ [W1l;W1r] + b1) [128]
//   L2: t = h@W2l [64]; hr = h@W2r + b2 [64]; out = segmean(t) + hr
// GEMMs via mma.sync bf16 hi/lo 3-pass (fp32 accum), generic-PTX-legal on sm_103.

#define MAXN 100000
#define MAXE 1600000

__device__ int   g_is64;
__device__ int   g_src[MAXE];
__device__ int   g_dst[MAXE];
__device__ int   g_cnt[MAXN];
__device__ int   g_row[MAXN + 1];
__device__ int   g_next[MAXN];
__device__ int   g_col[MAXE];
__device__ int   g_bs[1024];
__device__ int   g_bo[1024];
__device__ float g_agg[MAXN * 64];
__device__ float g_h[MAXN * 128];
__device__ float g_t[MAXN * 64];
// converted weight tile for current layer: [n:128][k:64 words] hi, then lo
__device__ uint32_t g_wb[2 * 128 * 64];

// ---------------- edge dtype detect ----------------

__global__ void k_detect(const int* __restrict__ ei32, int E) {
    if (threadIdx.x == 0 && blockIdx.x == 0) {
        int s = 0;
        #pragma unroll
        for (int i = 0; i < 64; i++) s |= ei32[2 * i + 1];
        g_is64 = (s == 0) ? 1 : 0;
    }
}

// ---------------- CSR build ----------------

__global__ void k_zero(int n) {
    int i = blockIdx.x * blockDim.x + threadIdx.x;
    if (i < n) g_cnt[i] = 0;
}

__global__ void k_hist(const void* __restrict__ ei, int E, int n) {
    int e = blockIdx.x * blockDim.x + threadIdx.x;
    if (e >= E) return;
    int s, d;
    if (g_is64) {
        const long long* p = (const long long*)ei;
        s = (int)p[e];
        d = (int)p[E + e];
    } else {
        const int* p = (const int*)ei;
        s = p[e];
        d = p[E + e];
    }
    s = min(max(s, 0), n - 1);
    d = min(max(d, 0), n - 1);
    g_src[e] = s;
    g_dst[e] = d;
    atomicAdd(&g_cnt[d], 1);
}

__global__ void k_scanA(int n) {
    __shared__ int s[1024];
    int i = blockIdx.x * 1024 + threadIdx.x;
    int v = (i < n) ? g_cnt[i] : 0;
    s[threadIdx.x] = v;
    __syncthreads();
    for (int off = 1; off < 1024; off <<= 1) {
        int t = (threadIdx.x >= off) ? s[threadIdx.x - off] : 0;
        __syncthreads();
        s[threadIdx.x] += t;
        __syncthreads();
    }
    if (i < n) g_row[i] = s[threadIdx.x] - v;
    if (threadIdx.x == 1023) g_bs[blockIdx.x] = s[1023];
}

__global__ void k_scanB(int nb) {
    __shared__ int s[1024];
    int v = (threadIdx.x < nb) ? g_bs[threadIdx.x] : 0;
    s[threadIdx.x] = v;
    __syncthreads();
    for (int off = 1; off < 1024; off <<= 1) {
        int t = (threadIdx.x >= off) ? s[threadIdx.x - off] : 0;
        __syncthreads();
        s[threadIdx.x] += t;
        __syncthreads();
    }
    g_bo[threadIdx.x] = s[threadIdx.x] - v;
}

__global__ void k_scanC(int n, int E) {
    int i = blockIdx.x * blockDim.x + threadIdx.x;
    if (i < n) {
        int r = g_row[i] + g_bo[i >> 10];
        g_row[i] = r;
        g_next[i] = r;
    }
    if (i == 0) g_row[n] = E;
}

__global__ void k_fill(int E) {
    int e = blockIdx.x * blockDim.x + threadIdx.x;
    if (e < E) {
        int p = atomicAdd(&g_next[g_dst[e]], 1);
        g_col[p] = g_src[e];
    }
}

// ---------------- segment mean (64 features, 1 warp / node) ----------------

__global__ void k_aggmean(const float* __restrict__ src, float* __restrict__ dstArr, int n) {
    int w = (blockIdx.x * blockDim.x + threadIdx.x) >> 5;
    int lane = threadIdx.x & 31;
    if (w >= n) return;
    int beg = g_row[w], end = g_row[w + 1];
    const float2* s2 = (const float2*)src;
    float sx = 0.f, sy = 0.f;
    int j = beg;
    for (; j + 4 <= end; j += 4) {
        int c0 = __ldg(&g_col[j]);
        int c1 = __ldg(&g_col[j + 1]);
        int c2 = __ldg(&g_col[j + 2]);
        int c3 = __ldg(&g_col[j + 3]);
        float2 v0 = __ldg(&s2[c0 * 32 + lane]);
        float2 v1 = __ldg(&s2[c1 * 32 + lane]);
        float2 v2 = __ldg(&s2[c2 * 32 + lane]);
        float2 v3 = __ldg(&s2[c3 * 32 + lane]);
        sx += v0.x + v1.x + v2.x + v3.x;
        sy += v0.y + v1.y + v2.y + v3.y;
    }
    for (; j < end; j++) {
        int c = __ldg(&g_col[j]);
        float2 v = __ldg(&s2[c * 32 + lane]);
        sx += v.x;
        sy += v.y;
    }
    int deg = end - beg;
    float inv = 1.0f / (float)(deg > 0 ? deg : 1);
    float2 o;
    o.x = sx * inv;
    o.y = sy * inv;
    ((float2*)dstArr)[w * 32 + lane] = o;
}

__global__ void k_aggmean_add(const float* __restrict__ src, float* __restrict__ out, int n) {
    int w = (blockIdx.x * blockDim.x + threadIdx.x) >> 5;
    int lane = threadIdx.x & 31;
    if (w >= n) return;
    int beg = g_row[w], end = g_row[w + 1];
    const float2* s2 = (const float2*)src;
    float sx = 0.f, sy = 0.f;
    int j = beg;
    for (; j + 4 <= end; j += 4) {
        int c0 = __ldg(&g_col[j]);
        int c1 = __ldg(&g_col[j + 1]);
        int c2 = __ldg(&g_col[j + 2]);
        int c3 = __ldg(&g_col[j + 3]);
        float2 v0 = __ldg(&s2[c0 * 32 + lane]);
        float2 v1 = __ldg(&s2[c1 * 32 + lane]);
        float2 v2 = __ldg(&s2[c2 * 32 + lane]);
        float2 v3 = __ldg(&s2[c3 * 32 + lane]);
        sx += v0.x + v1.x + v2.x + v3.x;
        sy += v0.y + v1.y + v2.y + v3.y;
    }
    for (; j < end; j++) {
        int c = __ldg(&g_col[j]);
        float2 v = __ldg(&s2[c * 32 + lane]);
        sx += v.x;
        sy += v.y;
    }
    int deg = end - beg;
    float inv = 1.0f / (float)(deg > 0 ? deg : 1);
    float2* o2 = (float2*)out;
    float2 cur = o2[w * 32 + lane];
    cur.x += sx * inv;
    cur.y += sy * inv;
    o2[w * 32 + lane] = cur;
}

// ---------------- weight tile precompute: g_wb = hi/lo bf16 of B[n][k] ----------------
// mode 0: B[n][k] (n<128, k<128): k<64 -> W1l[k][n] (64x128), k>=64 -> W1r[k-64][n]
// mode 1: n<64 -> W2l[k][n] (128x64), n>=64 -> W2r[k][n-64]

__device__ __forceinline__ uint32_t pack_hi(float a, float b) {
    __nv_bfloat16 h0 = __float2bfloat16(a);
    __nv_bfloat16 h1 = __float2bfloat16(b);
    return (uint32_t)__bfloat16_as_ushort(h0) | ((uint32_t)__bfloat16_as_ushort(h1) << 16);
}
__device__ __forceinline__ uint32_t pack_lo(float a, float b) {
    __nv_bfloat16 h0 = __float2bfloat16(a);
    __nv_bfloat16 h1 = __float2bfloat16(b);
    __nv_bfloat16 l0 = __float2bfloat16(a - __bfloat162float(h0));
    __nv_bfloat16 l1 = __float2bfloat16(b - __bfloat162float(h1));
    return (uint32_t)__bfloat16_as_ushort(l0) | ((uint32_t)__bfloat16_as_ushort(l1) << 16);
}

__global__ void k_wconv(int mode, const float* __restrict__ Wl, const float* __restrict__ Wr) {
    int i = blockIdx.x * blockDim.x + threadIdx.x;  // 0 .. 128*64
    if (i >= 128 * 64) return;
    int nn = i >> 6;
    int k = (i & 63) * 2;
    float w0, w1;
    if (mode == 0) {
        w0 = (k < 64) ? Wl[k * 128 + nn] : Wr[(k - 64) * 128 + nn];
        w1 = (k + 1 < 64) ? Wl[(k + 1) * 128 + nn] : Wr[(k + 1 - 64) * 128 + nn];
    } else {
        const float* W = (nn < 64) ? Wl : Wr;
        int c = (nn < 64) ? nn : nn - 64;
        w0 = W[k * 64 + c];
        w1 = W[(k + 1) * 64 + c];
    }
    g_wb[i] = pack_hi(w0, w1);
    g_wb[128 * 64 + i] = pack_lo(w0, w1);
}

// ---------------- GEMM via mma.sync bf16 hi/lo: D[128,128] = A @ B^T ----------------
// mode 0: A = [agg|x] (K=128), epilogue h = relu(D + b1)
// mode 1: A = h, epilogue cols<64 -> t = D, cols>=64 -> out = D + b2

#define KW 68          // padded row stride in 32-bit words (136 bf16)
#define SM_AH 0
#define SM_AL (128 * KW)
#define SM_BH (2 * 128 * KW)
#define SM_BL (3 * 128 * KW)
#define SMEM_MMA_BYTES (4 * 128 * KW * 4)

__global__ void __launch_bounds__(256, 1)
k_mma(int mode, const float* __restrict__ A0, const float* __restrict__ A1,
      const float* __restrict__ bias, float* __restrict__ O0, float* __restrict__ O1, int n)
{
    extern __shared__ uint32_t sm4[];
    int tid = threadIdx.x, wid = tid >> 5, lane = tid & 31;
    int row0 = blockIdx.x * 128;

    // ---- A tile: fp32 -> bf16 hi/lo ----
    for (int i = tid; i < 128 * 64; i += 256) {
        int m = i >> 6, kw = i & 63;
        int row = row0 + m;
        float2 v = make_float2(0.f, 0.f);
        if (row < n) {
            if (mode == 0)
                v = (kw < 32) ? __ldg(&((const float2*)A0)[row * 32 + kw])
                              : __ldg(&((const float2*)A1)[row * 32 + (kw - 32)]);
            else
                v = __ldg(&((const float2*)A0)[row * 64 + kw]);
        }
        sm4[SM_AH + m * KW + kw] = pack_hi(v.x, v.y);
        sm4[SM_AL + m * KW + kw] = pack_lo(v.x, v.y);
    }
    // ---- B tile: coalesced copy from precomputed g_wb ----
    for (int i = tid; i < 128 * 64; i += 256) {
        int nn = i >> 6, kw = i & 63;
        sm4[SM_BH + nn * KW + kw] = g_wb[i];
        sm4[SM_BL + nn * KW + kw] = g_wb[128 * 64 + i];
    }
    __syncthreads();

    // warp tiling: warp_m = wid&3 (32 rows), warp_n = wid>>2 (64 cols)
    int warp_m = wid & 3, warp_n = wid >> 2;
    int lr = lane >> 2;       // 0..7
    int lc = lane & 3;        // 0..3

    float acc[2][8][4];
    #pragma unroll
    for (int mt = 0; mt < 2; mt++)
        #pragma unroll
        for (int nt = 0; nt < 8; nt++)
            #pragma unroll
            for (int q = 0; q < 4; q++) acc[mt][nt][q] = 0.f;

    // passes: (Ah,Bh), (Ah,Bl), (Al,Bh)
    #pragma unroll 1
    for (int pass = 0; pass < 3; pass++) {
        const uint32_t* Ap = sm4 + ((pass == 2) ? SM_AL : SM_AH);
        const uint32_t* Bp = sm4 + ((pass == 1) ? SM_BL : SM_BH);
        #pragma unroll 2
        for (int ks = 0; ks < 8; ks++) {
            int kb = ks * 8 + lc;  // word offset within row
            uint32_t a[2][4];
            #pragma unroll
            for (int mt = 0; mt < 2; mt++) {
                int r = warp_m * 32 + mt * 16 + lr;
                a[mt][0] = Ap[r * KW + kb];
                a[mt][1] = Ap[(r + 8) * KW + kb];
                a[mt][2] = Ap[r * KW + kb + 4];
                a[mt][3] = Ap[(r + 8) * KW + kb + 4];
            }
            #pragma unroll
            for (int nt = 0; nt < 8; nt++) {
                int nb = warp_n * 64 + nt * 8 + lr;
                uint32_t b0 = Bp[nb * KW + kb];
                uint32_t b1 = Bp[nb * KW + kb + 4];
                #pragma unroll
                for (int mt = 0; mt < 2; mt++) {
                    asm volatile(
                        "mma.sync.aligned.m16n8k16.row.col.f32.bf16.bf16.f32 "
                        "{%0,%1,%2,%3}, {%4,%5,%6,%7}, {%8,%9}, {%0,%1,%2,%3};"
                        : "+f"(acc[mt][nt][0]), "+f"(acc[mt][nt][1]),
                          "+f"(acc[mt][nt][2]), "+f"(acc[mt][nt][3])
                        : "r"(a[mt][0]), "r"(a[mt][1]), "r"(a[mt][2]), "r"(a[mt][3]),
                          "r"(b0), "r"(b1));
                }
            }
        }
    }

    // ---- epilogue ----
    #pragma unroll
    for (int mt = 0; mt < 2; mt++) {
        int rbase = row0 + warp_m * 32 + mt * 16 + lr;
        #pragma unroll
        for (int nt = 0; nt < 8; nt++) {
            int col = warp_n * 64 + nt * 8 + lc * 2;
            #pragma unroll
            for (int half = 0; half < 2; half++) {
                int row = rbase + half * 8;
                if (row >= n) continue;
                float v0 = acc[mt][nt][half * 2 + 0];
                float v1 = acc[mt][nt][half * 2 + 1];
                if (mode == 0) {
                    v0 = fmaxf(v0 + __ldg(&bias[col]), 0.f);
                    v1 = fmaxf(v1 + __ldg(&bias[col + 1]), 0.f);
                    *(float2*)&O0[row * 128 + col] = make_float2(v0, v1);
                } else if (warp_n == 0) {
                    *(float2*)&O0[row * 64 + col] = make_float2(v0, v1);
                } else {
                    int cb = col - 64;
                    v0 += __ldg(&bias[cb]);
                    v1 += __ldg(&bias[cb + 1]);
                    *(float2*)&O1[row * 64 + cb] = make_float2(v0, v1);
                }
            }
        }
    }
}

// ---------------- launch ----------------

extern "C" void kernel_launch(void* const* d_in, const int* in_sizes, int n_in,
                              void* d_out, int out_size) {
    const float* x = (const float*)d_in[0];
    const void* ei = d_in[1];
    const float* W1l = (const float*)d_in[2];
    const float* W1r = (const float*)d_in[3];
    const float* b1 = (const float*)d_in[4];
    const float* W2l = (const float*)d_in[5];
    const float* W2r = (const float*)d_in[6];
    const float* b2 = (const float*)d_in[7];
    float* out = (float*)d_out;

    int n = in_sizes[0] / 64;
    int E = in_sizes[1] / 2;

    float* agg;  cudaGetSymbolAddress((void**)&agg, g_agg);
    float* h;    cudaGetSymbolAddress((void**)&h, g_h);
    float* t;    cudaGetSymbolAddress((void**)&t, g_t);

    cudaFuncSetAttribute(k_mma, cudaFuncAttributeMaxDynamicSharedMemorySize, SMEM_MMA_BYTES);

    int nb = (n + 1023) / 1024;
    int ntile = (n + 127) / 128;

    k_detect<<<1, 32>>>((const int*)ei, E);
    k_zero<<<(n + 255) / 256, 256>>>(n);
    k_hist<<<(E + 255) / 256, 256>>>(ei, E, n);
    k_scanA<<<nb, 1024>>>(n);
    k_scanB<<<1, 1024>>>(nb);
    k_scanC<<<(n + 255) / 256, 256>>>(n, E);
    k_fill<<<(E + 255) / 256, 256>>>(E);

    // layer 1
    k_aggmean<<<(n * 32 + 255) / 256, 256>>>(x, agg, n);
    k_wconv<<<32, 256>>>(0, W1l, W1r);
    k_mma<<<ntile, 256, SMEM_MMA_BYTES>>>(0, agg, x, b1, h, nullptr, n);

    // layer 2
    k_wconv<<<32, 256>>>(1, W2l, W2r);
    k_mma<<<ntile, 256, SMEM_MMA_BYTES>>>(1, h, nullptr, b2, t, out, n);
    k_aggmean_add<<<(n * 32 + 255) / 256, 256>>>(t, out, n);
}

// round 9
// speedup vs baseline: 1.4888x; 1.4888x over previous
#include <cuda_runtime.h>
#include <cuda_fp16.h>
#include <cstdint>

// GraphSAGE 2-layer.
//   L1: agg1 = segmean(x) [64]; h = relu([agg1|x] @ [W1l;W1r] + b1) [128]
//   L2: t = h@W2l [64]; hr = h@W2r + b2 [64]; out = segmean(t) + hr
// GEMMs: mma.sync m16n8k16 fp16, A split hi/lo (2 passes), B hi-only. fp32 accum.

#define MAXN 100000
#define MAXE 1600000

__device__ int   g_is64;
__device__ int   g_src[MAXE];
__device__ int   g_dst[MAXE];
__device__ int   g_cnt[MAXN];
__device__ int   g_row[MAXN + 1];
__device__ int   g_next[MAXN];
__device__ int   g_col[MAXE];
__device__ int   g_bs[1024];
__device__ int   g_bo[1024];
__device__ float g_agg[MAXN * 64];
__device__ float g_h[MAXN * 128];
__device__ float g_t[MAXN * 64];
// fp16-hi weight tile for current layer: [n:128][kw:64 words]
__device__ uint32_t g_wb[128 * 64];

// ---------------- edge dtype detect ----------------

__global__ void k_detect(const int* __restrict__ ei32, int E) {
    if (threadIdx.x == 0 && blockIdx.x == 0) {
        int s = 0;
        #pragma unroll
        for (int i = 0; i < 64; i++) s |= ei32[2 * i + 1];
        g_is64 = (s == 0) ? 1 : 0;
    }
}

// ---------------- CSR build ----------------

__global__ void k_zero(int n) {
    int i = blockIdx.x * blockDim.x + threadIdx.x;
    if (i < n) g_cnt[i] = 0;
}

__global__ void k_hist(const void* __restrict__ ei, int E, int n) {
    int e = blockIdx.x * blockDim.x + threadIdx.x;
    if (e >= E) return;
    int s, d;
    if (g_is64) {
        const long long* p = (const long long*)ei;
        s = (int)p[e];
        d = (int)p[E + e];
    } else {
        const int* p = (const int*)ei;
        s = p[e];
        d = p[E + e];
    }
    s = min(max(s, 0), n - 1);
    d = min(max(d, 0), n - 1);
    g_src[e] = s;
    g_dst[e] = d;
    atomicAdd(&g_cnt[d], 1);
}

__global__ void k_scanA(int n) {
    __shared__ int s[1024];
    int i = blockIdx.x * 1024 + threadIdx.x;
    int v = (i < n) ? g_cnt[i] : 0;
    s[threadIdx.x] = v;
    __syncthreads();
    for (int off = 1; off < 1024; off <<= 1) {
        int t = (threadIdx.x >= off) ? s[threadIdx.x - off] : 0;
        __syncthreads();
        s[threadIdx.x] += t;
        __syncthreads();
    }
    if (i < n) g_row[i] = s[threadIdx.x] - v;
    if (threadIdx.x == 1023) g_bs[blockIdx.x] = s[1023];
}

__global__ void k_scanB(int nb) {
    __shared__ int s[1024];
    int v = (threadIdx.x < nb) ? g_bs[threadIdx.x] : 0;
    s[threadIdx.x] = v;
    __syncthreads();
    for (int off = 1; off < 1024; off <<= 1) {
        int t = (threadIdx.x >= off) ? s[threadIdx.x - off] : 0;
        __syncthreads();
        s[threadIdx.x] += t;
        __syncthreads();
    }
    g_bo[threadIdx.x] = s[threadIdx.x] - v;
}

__global__ void k_scanC(int n, int E) {
    int i = blockIdx.x * blockDim.x + threadIdx.x;
    if (i < n) {
        int r = g_row[i] + g_bo[i >> 10];
        g_row[i] = r;
        g_next[i] = r;
    }
    if (i == 0) g_row[n] = E;
}

__global__ void k_fill(int E) {
    int e = blockIdx.x * blockDim.x + threadIdx.x;
    if (e < E) {
        int p = atomicAdd(&g_next[g_dst[e]], 1);
        g_col[p] = g_src[e];
    }
}

// ---------------- segment mean (64 features, 1 warp / node) ----------------

__global__ void k_aggmean(const float* __restrict__ src, float* __restrict__ dstArr, int n) {
    int w = (blockIdx.x * blockDim.x + threadIdx.x) >> 5;
    int lane = threadIdx.x & 31;
    if (w >= n) return;
    int beg = g_row[w], end = g_row[w + 1];
    const float2* s2 = (const float2*)src;
    float sx = 0.f, sy = 0.f;
    int j = beg;
    for (; j + 4 <= end; j += 4) {
        int c0 = __ldg(&g_col[j]);
        int c1 = __ldg(&g_col[j + 1]);
        int c2 = __ldg(&g_col[j + 2]);
        int c3 = __ldg(&g_col[j + 3]);
        float2 v0 = __ldg(&s2[c0 * 32 + lane]);
        float2 v1 = __ldg(&s2[c1 * 32 + lane]);
        float2 v2 = __ldg(&s2[c2 * 32 + lane]);
        float2 v3 = __ldg(&s2[c3 * 32 + lane]);
        sx += v0.x + v1.x + v2.x + v3.x;
        sy += v0.y + v1.y + v2.y + v3.y;
    }
    for (; j < end; j++) {
        int c = __ldg(&g_col[j]);
        float2 v = __ldg(&s2[c * 32 + lane]);
        sx += v.x;
        sy += v.y;
    }
    int deg = end - beg;
    float inv = 1.0f / (float)(deg > 0 ? deg : 1);
    float2 o;
    o.x = sx * inv;
    o.y = sy * inv;
    ((float2*)dstArr)[w * 32 + lane] = o;
}

__global__ void k_aggmean_add(const float* __restrict__ src, float* __restrict__ out, int n) {
    int w = (blockIdx.x * blockDim.x + threadIdx.x) >> 5;
    int lane = threadIdx.x & 31;
    if (w >= n) return;
    int beg = g_row[w], end = g_row[w + 1];
    const float2* s2 = (const float2*)src;
    float sx = 0.f, sy = 0.f;
    int j = beg;
    for (; j + 4 <= end; j += 4) {
        int c0 = __ldg(&g_col[j]);
        int c1 = __ldg(&g_col[j + 1]);
        int c2 = __ldg(&g_col[j + 2]);
        int c3 = __ldg(&g_col[j + 3]);
        float2 v0 = __ldg(&s2[c0 * 32 + lane]);
        float2 v1 = __ldg(&s2[c1 * 32 + lane]);
        float2 v2 = __ldg(&s2[c2 * 32 + lane]);
        float2 v3 = __ldg(&s2[c3 * 32 + lane]);
        sx += v0.x + v1.x + v2.x + v3.x;
        sy += v0.y + v1.y + v2.y + v3.y;
    }
    for (; j < end; j++) {
        int c = __ldg(&g_col[j]);
        float2 v = __ldg(&s2[c * 32 + lane]);
        sx += v.x;
        sy += v.y;
    }
    int deg = end - beg;
    float inv = 1.0f / (float)(deg > 0 ? deg : 1);
    float2* o2 = (float2*)out;
    float2 cur = o2[w * 32 + lane];
    cur.x += sx * inv;
    cur.y += sy * inv;
    o2[w * 32 + lane] = cur;
}

// ---------------- weight precompute: g_wb = fp16-hi of B[n][k] ----------------

__device__ __forceinline__ uint32_t pack_h(float a, float b) {
    __half h0 = __float2half_rn(a);
    __half h1 = __float2half_rn(b);
    return (uint32_t)__half_as_ushort(h0) | ((uint32_t)__half_as_ushort(h1) << 16);
}

__global__ void k_wconv(int mode, const float* __restrict__ Wl, const float* __restrict__ Wr) {
    int i = blockIdx.x * blockDim.x + threadIdx.x;
    if (i >= 128 * 64) return;
    int nn = i >> 6;
    int k = (i & 63) * 2;
    float w0, w1;
    if (mode == 0) {
        w0 = (k < 64) ? Wl[k * 128 + nn] : Wr[(k - 64) * 128 + nn];
        w1 = (k + 1 < 64) ? Wl[(k + 1) * 128 + nn] : Wr[(k + 1 - 64) * 128 + nn];
    } else {
        const float* W = (nn < 64) ? Wl : Wr;
        int c = (nn < 64) ? nn : nn - 64;
        w0 = W[k * 64 + c];
        w1 = W[(k + 1) * 64 + c];
    }
    g_wb[i] = pack_h(w0, w1);
}

// ---------------- GEMM: D[128,128] = A @ B^T, fp16 A-hi/lo 2-pass ----------------
// mode 0: A = [agg|x], epilogue h = relu(D + b1)
// mode 1: A = h, epilogue cols<64 -> t = D, cols>=64 -> out = D + b2

#define KW 68  // row stride in 32-bit words (payload 64 = 128 fp16 k-values)
#define SM_AH 0
#define SM_AL (128 * KW)
#define SM_BH (2 * 128 * KW)
#define SM_BIAS (3 * 128 * KW)
#define SMEM_WORDS (3 * 128 * KW + 128)
#define SMEM_MMA_BYTES (SMEM_WORDS * 4)

__global__ void __launch_bounds__(256, 2)
k_mma(int mode, const float* __restrict__ A0, const float* __restrict__ A1,
      const float* __restrict__ bias, float* __restrict__ O0, float* __restrict__ O1, int n)
{
    extern __shared__ uint32_t sm4[];
    int tid = threadIdx.x, wid = tid >> 5, lane = tid & 31;
    int row0 = blockIdx.x * 128;

    // ---- A tile: fp32 -> fp16 hi/lo ----
    for (int i = tid; i < 128 * 64; i += 256) {
        int m = i >> 6, kw = i & 63;
        int row = row0 + m;
        float2 v = make_float2(0.f, 0.f);
        if (row < n) {
            if (mode == 0)
                v = (kw < 32) ? __ldg(&((const float2*)A0)[row * 32 + kw])
                              : __ldg(&((const float2*)A1)[row * 32 + (kw - 32)]);
            else
                v = __ldg(&((const float2*)A0)[row * 64 + kw]);
        }
        __half h0 = __float2half_rn(v.x);
        __half h1 = __float2half_rn(v.y);
        __half l0 = __float2half_rn(v.x - __half2float(h0));
        __half l1 = __float2half_rn(v.y - __half2float(h1));
        sm4[SM_AH + m * KW + kw] = (uint32_t)__half_as_ushort(h0) | ((uint32_t)__half_as_ushort(h1) << 16);
        sm4[SM_AL + m * KW + kw] = (uint32_t)__half_as_ushort(l0) | ((uint32_t)__half_as_ushort(l1) << 16);
    }
    // ---- B tile (hi only): coalesced copy ----
    for (int i = tid; i < 128 * 64; i += 256) {
        int nn = i >> 6, kw = i & 63;
        sm4[SM_BH + nn * KW + kw] = g_wb[i];
    }
    if (tid < 128) {
        float bv = 0.f;
        if (mode == 0) bv = __ldg(&bias[tid]);
        else if (tid < 64) bv = __ldg(&bias[tid]);
        ((float*)(sm4 + SM_BIAS))[tid] = bv;
    }
    __syncthreads();

    int warp_m = wid & 3, warp_n = wid >> 2;
    int lr = lane >> 2;  // 0..7
    int lc = lane & 3;   // 0..3

    float acc[2][8][4];
    #pragma unroll
    for (int mt = 0; mt < 2; mt++)
        #pragma unroll
        for (int nt = 0; nt < 8; nt++)
            #pragma unroll
            for (int q = 0; q < 4; q++) acc[mt][nt][q] = 0.f;

    // ldmatrix lane-address components
    int a_row_in_tile = lane & 15;          // + mt*16 + warp_m*32
    int a_kw_off = (lane >> 4) << 2;        // 0 or 4 words
    int b_row_in_grp = (lane & 7) + ((lane >> 4) << 3);  // n within 16-group
    int b_kw_off = ((lane >> 3) & 1) << 2;  // 0 or 4 words

    #pragma unroll 1
    for (int pass = 0; pass < 2; pass++) {
        const uint32_t* Ap = sm4 + ((pass == 0) ? SM_AH : SM_AL);
        const uint32_t* Bp = sm4 + SM_BH;
        #pragma unroll
        for (int ks = 0; ks < 8; ks++) {
            int kwb = ks * 8;
            uint32_t a[2][4];
            #pragma unroll
            for (int mt = 0; mt < 2; mt++) {
                int r = warp_m * 32 + mt * 16 + a_row_in_tile;
                uint32_t addr = (uint32_t)__cvta_generic_to_shared(&Ap[r * KW + kwb + a_kw_off]);
                asm volatile("ldmatrix.sync.aligned.m8n8.x4.shared.b16 {%0,%1,%2,%3}, [%4];"
                             : "=r"(a[mt][0]), "=r"(a[mt][1]), "=r"(a[mt][2]), "=r"(a[mt][3])
                             : "r"(addr));
            }
            uint32_t br[4][4];
            #pragma unroll
            for (int ng = 0; ng < 4; ng++) {
                int nb = warp_n * 64 + ng * 16 + b_row_in_grp;
                uint32_t addr = (uint32_t)__cvta_generic_to_shared(&Bp[nb * KW + kwb + b_kw_off]);
                asm volatile("ldmatrix.sync.aligned.m8n8.x4.shared.b16 {%0,%1,%2,%3}, [%4];"
                             : "=r"(br[ng][0]), "=r"(br[ng][1]), "=r"(br[ng][2]), "=r"(br[ng][3])
                             : "r"(addr));
            }
            #pragma unroll
            for (int ng = 0; ng < 4; ng++) {
                #pragma unroll
                for (int sub = 0; sub < 2; sub++) {
                    int nt = ng * 2 + sub;
                    uint32_t b0 = br[ng][sub * 2], b1 = br[ng][sub * 2 + 1];
                    #pragma unroll
                    for (int mt = 0; mt < 2; mt++) {
                        asm volatile(
                            "mma.sync.aligned.m16n8k16.row.col.f32.f16.f16.f32 "
                            "{%0,%1,%2,%3}, {%4,%5,%6,%7}, {%8,%9}, {%0,%1,%2,%3};"
                            : "+f"(acc[mt][nt][0]), "+f"(acc[mt][nt][1]),
                              "+f"(acc[mt][nt][2]), "+f"(acc[mt][nt][3])
                            : "r"(a[mt][0]), "r"(a[mt][1]), "r"(a[mt][2]), "r"(a[mt][3]),
                              "r"(b0), "r"(b1));
                    }
                }
            }
        }
    }

    // ---- epilogue ----
    const float* sb = (const float*)(sm4 + SM_BIAS);
    #pragma unroll
    for (int mt = 0; mt < 2; mt++) {
        int rbase = row0 + warp_m * 32 + mt * 16 + lr;
        #pragma unroll
        for (int nt = 0; nt < 8; nt++) {
            int col = warp_n * 64 + nt * 8 + lc * 2;
            #pragma unroll
            for (int half = 0; half < 2; half++) {
                int row = rbase + half * 8;
                if (row >= n) continue;
                float v0 = acc[mt][nt][half * 2 + 0];
                float v1 = acc[mt][nt][half * 2 + 1];
                if (mode == 0) {
                    v0 = fmaxf(v0 + sb[col], 0.f);
                    v1 = fmaxf(v1 + sb[col + 1], 0.f);
                    *(float2*)&O0[row * 128 + col] = make_float2(v0, v1);
                } else if (warp_n == 0) {
                    *(float2*)&O0[row * 64 + col] = make_float2(v0, v1);
                } else {
                    int cb = col - 64;
                    v0 += sb[cb];
                    v1 += sb[cb + 1];
                    *(float2*)&O1[row * 64 + cb] = make_float2(v0, v1);
                }
            }
        }
    }
}

// ---------------- launch ----------------

extern "C" void kernel_launch(void* const* d_in, const int* in_sizes, int n_in,
                              void* d_out, int out_size) {
    const float* x = (const float*)d_in[0];
    const void* ei = d_in[1];
    const float* W1l = (const float*)d_in[2];
    const float* W1r = (const float*)d_in[3];
    const float* b1 = (const float*)d_in[4];
    const float* W2l = (const float*)d_in[5];
    const float* W2r = (const float*)d_in[6];
    const float* b2 = (const float*)d_in[7];
    float* out = (float*)d_out;

    int n = in_sizes[0] / 64;
    int E = in_sizes[1] / 2;

    float* agg;  cudaGetSymbolAddress((void**)&agg, g_agg);
    float* h;    cudaGetSymbolAddress((void**)&h, g_h);
    float* t;    cudaGetSymbolAddress((void**)&t, g_t);

    cudaFuncSetAttribute(k_mma, cudaFuncAttributeMaxDynamicSharedMemorySize, SMEM_MMA_BYTES);

    int nb = (n + 1023) / 1024;
    int ntile = (n + 127) / 128;

    k_detect<<<1, 32>>>((const int*)ei, E);
    k_zero<<<(n + 255) / 256, 256>>>(n);
    k_hist<<<(E + 255) / 256, 256>>>(ei, E, n);
    k_scanA<<<nb, 1024>>>(n);
    k_scanB<<<1, 1024>>>(nb);
    k_scanC<<<(n + 255) / 256, 256>>>(n, E);
    k_fill<<<(E + 255) / 256, 256>>>(E);

    // layer 1
    k_aggmean<<<(n * 32 + 255) / 256, 256>>>(x, agg, n);
    k_wconv<<<32, 256>>>(0, W1l, W1r);
    k_mma<<<ntile, 256, SMEM_MMA_BYTES>>>(0, agg, x, b1, h, nullptr, n);

    // layer 2
    k_wconv<<<32, 256>>>(1, W2l, W2r);
    k_mma<<<ntile, 256, SMEM_MMA_BYTES>>>(1, h, nullptr, b2, t, out, n);
    k_aggmean_add<<<(n * 32 + 255) / 256, 256>>>(t, out, n);
}